// round 16
// baseline (speedup 1.0000x reference)
#include <cuda_runtime.h>
#include <cuda_bf16.h>
#include <cstdint>
#include <math.h>

#define BB   4
#define WW   256
#define CSEQ 32
#define CDIM 1024
#define NH   16
#define HD   64
#define BW   1024

typedef unsigned long long ull;

// Scratch (device globals: allocation-free rule)
__device__ float g_t [(size_t)BW * NH * CDIM];
__device__ __nv_bfloat16 g_Ah[(size_t)BW * NH * CDIM];
__device__ __nv_bfloat16 g_Al[(size_t)BW * NH * CDIM];
__device__ __nv_bfloat16 g_oh[(size_t)BW * CDIM];
__device__ __nv_bfloat16 g_ol[(size_t)BW * CDIM];
// pre-split weight planes: [0]=Wq^T, [1]=proj^T, [2]=Wv^T, [3]=Wk  (each [1024][1024])
__device__ __nv_bfloat16 g_Wh[4 * (size_t)CDIM * CDIM];
__device__ __nv_bfloat16 g_Wl[4 * (size_t)CDIM * CDIM];
__device__ int g_last[BW];

// ===========================================================================
__device__ __forceinline__ uint32_t smem_to_u32(const void* smem_ptr) {
    uint32_t addr;
    asm("{ .reg .u64 tmp; cvta.to.shared.u64 tmp, %1; cvt.u32.u64 %0, tmp; }"
        : "=r"(addr) : "l"(smem_ptr));
    return addr;
}
#define SMEM_SWIZZLE_128B(byte_offset) ((byte_offset) ^ (((byte_offset) >> 3) & 0x70))

__device__ __forceinline__ void mma_bf16(float* d, const uint32_t* a, const uint32_t* b) {
    asm volatile(
        "mma.sync.aligned.m16n8k16.row.col.f32.bf16.bf16.f32 "
        "{%0,%1,%2,%3}, {%4,%5,%6,%7}, {%8,%9}, {%0,%1,%2,%3};"
        : "+f"(d[0]), "+f"(d[1]), "+f"(d[2]), "+f"(d[3])
        : "r"(a[0]), "r"(a[1]), "r"(a[2]), "r"(a[3]), "r"(b[0]), "r"(b[1]));
}
__device__ __forceinline__ void ldsm4(uint32_t* r, uint32_t addr) {
    asm volatile("ldmatrix.sync.aligned.m8n8.x4.shared.b16 {%0,%1,%2,%3}, [%4];"
        : "=r"(r[0]), "=r"(r[1]), "=r"(r[2]), "=r"(r[3]) : "r"(addr));
}
__device__ __forceinline__ void ldsm4t(uint32_t* r, uint32_t addr) {
    asm volatile("ldmatrix.sync.aligned.m8n8.x4.trans.shared.b16 {%0,%1,%2,%3}, [%4];"
        : "=r"(r[0]), "=r"(r[1]), "=r"(r[2]), "=r"(r[3]) : "r"(addr));
}
__device__ __forceinline__ void cpa16(uint32_t dst, const void* src) {
    asm volatile("cp.async.cg.shared.global [%0], [%1], 16;" :: "r"(dst), "l"(src));
}
#define CP_COMMIT()  asm volatile("cp.async.commit_group;" ::: "memory")
#define CP_WAIT(n)   asm volatile("cp.async.wait_group %0;" :: "n"(n) : "memory")

// bf16 hi/lo split helpers
__device__ __forceinline__ uint32_t pkbf(__nv_bfloat16 a, __nv_bfloat16 b) {
    return (uint32_t)__bfloat16_as_ushort(a) | ((uint32_t)__bfloat16_as_ushort(b) << 16);
}
__device__ __forceinline__ void split_store(char* hi, char* lo, uint32_t sw, float4 v) {
    __nv_bfloat16 a0 = __float2bfloat16(v.x), a1 = __float2bfloat16(v.y),
                  a2 = __float2bfloat16(v.z), a3 = __float2bfloat16(v.w);
    float r0 = v.x - __bfloat162float(a0), r1 = v.y - __bfloat162float(a1),
          r2 = v.z - __bfloat162float(a2), r3 = v.w - __bfloat162float(a3);
    __nv_bfloat16 b0 = __float2bfloat16(r0), b1 = __float2bfloat16(r1),
                  b2 = __float2bfloat16(r2), b3 = __float2bfloat16(r3);
    *(uint2*)(hi + sw) = make_uint2(pkbf(a0, a1), pkbf(a2, a3));
    *(uint2*)(lo + sw) = make_uint2(pkbf(b0, b1), pkbf(b2, b3));
}
__device__ __forceinline__ void split1(float v, __nv_bfloat16* hi, __nv_bfloat16* lo) {
    __nv_bfloat16 h = __float2bfloat16(v);
    *hi = h;
    *lo = __float2bfloat16(v - __bfloat162float(h));
}

// ---------------------------------------------------------------------------
// Prep: z=0..2 transpose+split (Wq^T, proj^T, Wv^T), z=3 copy+split Wk, z=4 g_last.
__global__ __launch_bounds__(256)
void k_prep(const float* __restrict__ attn_w, const float* __restrict__ proj_w,
            const int* __restrict__ mask) {
    const int z = blockIdx.z;
    const int tx = threadIdx.x, ty = threadIdx.y;
    if (z == 4) {
        if (blockIdx.y == 0 && blockIdx.x < 4) {
            int i = blockIdx.x * 256 + ty * 32 + tx;
            int s = 0;
            #pragma unroll
            for (int j = 0; j < CSEQ; j++) s += mask[i * CSEQ + j];
            g_last[i] = s - 1;
        }
        return;
    }
    if (z == 3) {
        const int n0 = blockIdx.y * 32, k0 = blockIdx.x * 32;
        __nv_bfloat16* oh = g_Wh + 3 * (size_t)CDIM * CDIM;
        __nv_bfloat16* ol = g_Wl + 3 * (size_t)CDIM * CDIM;
        #pragma unroll
        for (int i = ty; i < 32; i += 8) {
            float v = attn_w[(size_t)(n0 + i) * 3072 + CDIM + k0 + tx];
            split1(v, oh + (size_t)(n0 + i) * CDIM + k0 + tx,
                      ol + (size_t)(n0 + i) * CDIM + k0 + tx);
        }
        return;
    }
    const float* in; int ldin;
    if (z == 0)      { in = attn_w;            ldin = 3 * CDIM; }
    else if (z == 1) { in = proj_w;            ldin = CDIM; }
    else             { in = attn_w + 2 * CDIM; ldin = 3 * CDIM; }
    __nv_bfloat16* oh = g_Wh + (size_t)z * CDIM * CDIM;
    __nv_bfloat16* ol = g_Wl + (size_t)z * CDIM * CDIM;

    __shared__ float t[32][33];
    const int k0 = blockIdx.y * 32, n0 = blockIdx.x * 32;
    #pragma unroll
    for (int i = ty; i < 32; i += 8)
        t[i][tx] = in[(size_t)(k0 + i) * ldin + n0 + tx];
    __syncthreads();
    #pragma unroll
    for (int i = ty; i < 32; i += 8) {
        float v = t[tx][i];
        split1(v, oh + (size_t)(n0 + i) * CDIM + k0 + tx,
                  ol + (size_t)(n0 + i) * CDIM + k0 + tx);
    }
}

// ---------------------------------------------------------------------------
// Fused Q+t kernel (R12, 256 threads). grid (1, 8, 16). t out: fp32.
#define QT_QHI 0
#define QT_QLO 16384
#define QT_A   32768
#define QT_S1B 65536
#define QT_S2B 98304
#define QT_SMEM (163840 + 1024)

__global__ __launch_bounds__(256)
void k_qt(const float* __restrict__ x,
          const __nv_bfloat16* __restrict__ Wqh, const __nv_bfloat16* __restrict__ Wql,
          const __nv_bfloat16* __restrict__ Wkh, const __nv_bfloat16* __restrict__ Wkl) {
    extern __shared__ char dsm[];
    const uint32_t raw = smem_to_u32(dsm);
    const uint32_t padb = (1024u - (raw & 1023u)) & 1023u;
    char* base = dsm + padb;
    const uint32_t sb = raw + padb;

    char* qhi = base + QT_QHI;
    char* qlo = base + QT_QLO;
    char* a_hi = base + QT_A;
    char* a_lo = base + QT_A + 16384;
    const uint32_t QHI_U = sb + QT_QHI, QLO_U = sb + QT_QLO;
    const uint32_t A_HI = sb + QT_A, A_LO = sb + QT_A + 16384;
    const uint32_t S1B = sb + QT_S1B;
    const uint32_t S2B = sb + QT_S2B;

    const int tid = threadIdx.x, wid = tid >> 5, lane = tid & 31;
    const int row0 = blockIdx.y * 128;
    const int h = blockIdx.z;

    const int a_row = lane & 15;
    const int a_kb  = (lane >> 4) * 16;
    const int b_row = (lane & 7) + ((lane >> 4) * 8);
    const int b_kb  = ((lane >> 3) & 1) * 16;

    // stage 1: q = gather(x) @ Wq_h
    {
        const int m_w = (wid >> 1) * 32;
        const int n_w = (wid & 1) * 32;
        float q4[2][4][4];
        #pragma unroll
        for (int i = 0; i < 2; i++)
            #pragma unroll
            for (int j = 0; j < 4; j++)
                #pragma unroll
                for (int q = 0; q < 4; q++) q4[i][j][q] = 0.f;

        const float* aptr[8];
        uint32_t aswz[8];
        #pragma unroll
        for (int i = 0; i < 8; i++) {
            int s = tid + i * 256;
            int r = s >> 4, kq = (s & 15) * 4;
            int grow = row0 + r;
            aptr[i] = x + ((size_t)grow * CSEQ + g_last[grow]) * CDIM + kq;
            aswz[i] = SMEM_SWIZZLE_128B((uint32_t)(r * 128 + kq * 2));
        }

        const __nv_bfloat16* bqh = Wqh + (size_t)h * HD * CDIM;
        const __nv_bfloat16* bql = Wql + (size_t)h * HD * CDIM;

        #pragma unroll
        for (int i = tid; i < 512; i += 256) {
            int r = i >> 3, g = i & 7;
            uint32_t dst = S1B + SMEM_SWIZZLE_128B((uint32_t)(r * 128 + g * 16));
            cpa16(dst,        bqh + (size_t)r * CDIM + g * 8);
            cpa16(dst + 8192, bql + (size_t)r * CDIM + g * 8);
        }
        CP_COMMIT();

        float4 ra[8];
        #pragma unroll
        for (int i = 0; i < 8; i++) ra[i] = *(const float4*)(aptr[i]);

        for (int ch = 0; ch < 16; ch++) {
            #pragma unroll
            for (int i = 0; i < 8; i++) split_store(a_hi, a_lo, aswz[i], ra[i]);

            if (ch + 1 < 16) {
                const uint32_t stg = (uint32_t)((ch + 1) & 1) * 16384;
                const int kb = (ch + 1) * 64;
                #pragma unroll
                for (int i = tid; i < 512; i += 256) {
                    int r = i >> 3, g = i & 7;
                    uint32_t dst = S1B + stg + SMEM_SWIZZLE_128B((uint32_t)(r * 128 + g * 16));
                    cpa16(dst,        bqh + (size_t)r * CDIM + kb + g * 8);
                    cpa16(dst + 8192, bql + (size_t)r * CDIM + kb + g * 8);
                }
                CP_COMMIT();
                CP_WAIT(1);
            } else {
                CP_WAIT(0);
            }
            __syncthreads();

            if (ch + 1 < 16) {
                const int kb = (ch + 1) << 6;
                #pragma unroll
                for (int i = 0; i < 8; i++) ra[i] = *(const float4*)(aptr[i] + kb);
            }

            const uint32_t BH = S1B + (uint32_t)(ch & 1) * 16384;
            const uint32_t BL = BH + 8192;

            #pragma unroll
            for (int ks = 0; ks < 4; ks++) {
                const int ksb = ks * 32;
                uint32_t bh[4][2], bl[4][2];
                #pragma unroll
                for (int p = 0; p < 2; p++) {
                    uint32_t sw = SMEM_SWIZZLE_128B(
                        (uint32_t)((n_w + p * 16 + b_row) * 128 + ksb + b_kb));
                    uint32_t r4[4];
                    ldsm4(r4, BH + sw);
                    bh[2*p][0] = r4[0]; bh[2*p][1] = r4[1];
                    bh[2*p+1][0] = r4[2]; bh[2*p+1][1] = r4[3];
                    ldsm4(r4, BL + sw);
                    bl[2*p][0] = r4[0]; bl[2*p][1] = r4[1];
                    bl[2*p+1][0] = r4[2]; bl[2*p+1][1] = r4[3];
                }
                uint32_t ah[2][4], al[2][4];
                #pragma unroll
                for (int mt = 0; mt < 2; mt++) {
                    uint32_t sw = SMEM_SWIZZLE_128B(
                        (uint32_t)((m_w + mt * 16 + a_row) * 128 + ksb + a_kb));
                    ldsm4(ah[mt], A_HI + sw);
                    ldsm4(al[mt], A_LO + sw);
                }
                #pragma unroll
                for (int mt = 0; mt < 2; mt++)
                    #pragma unroll
                    for (int nt = 0; nt < 4; nt++) {
                        mma_bf16(q4[mt][nt], ah[mt], bh[nt]);
                        mma_bf16(q4[mt][nt], ah[mt], bl[nt]);
                        mma_bf16(q4[mt][nt], al[mt], bh[nt]);
                    }
            }
            __syncthreads();
        }

        #pragma unroll
        for (int mt = 0; mt < 2; mt++) {
            const int r0 = m_w + mt * 16 + (lane >> 2);
            #pragma unroll
            for (int nt = 0; nt < 4; nt++) {
                const int c0 = n_w + nt * 8 + (lane & 3) * 2;
                __nv_bfloat16 h0, l0, h1, l1;
                split1(q4[mt][nt][0], &h0, &l0);
                split1(q4[mt][nt][1], &h1, &l1);
                uint32_t sw = SMEM_SWIZZLE_128B((uint32_t)(r0 * 128 + c0 * 2));
                *(uint32_t*)(qhi + sw) = pkbf(h0, h1);
                *(uint32_t*)(qlo + sw) = pkbf(l0, l1);
                split1(q4[mt][nt][2], &h0, &l0);
                split1(q4[mt][nt][3], &h1, &l1);
                sw = SMEM_SWIZZLE_128B((uint32_t)((r0 + 8) * 128 + c0 * 2));
                *(uint32_t*)(qhi + sw) = pkbf(h0, h1);
                *(uint32_t*)(qlo + sw) = pkbf(l0, l1);
            }
        }
    }
    __syncthreads();

    // stage 2: t = q @ Wk_h^T
    {
        const int m_w = (wid >> 2) * 64;
        const int n_w = (wid & 3) * 32;
        const __nv_bfloat16* bkh = Wkh + (size_t)h * HD;
        const __nv_bfloat16* bkl = Wkl + (size_t)h * HD;

        #pragma unroll
        for (int i = tid; i < 1024; i += 256) {
            int r = i >> 3, g = i & 7;
            uint32_t dst = S2B + SMEM_SWIZZLE_128B((uint32_t)(r * 128 + g * 16));
            cpa16(dst,         bkh + (size_t)r * CDIM + g * 8);
            cpa16(dst + 16384, bkl + (size_t)r * CDIM + g * 8);
        }
        CP_COMMIT();

        float* trow = g_t + (size_t)h * CDIM;

        for (int nc = 0; nc < 8; nc++) {
            if (nc + 1 < 8) {
                const uint32_t stg = (uint32_t)((nc + 1) & 1) * 32768;
                const int rb = (nc + 1) * 128;
                #pragma unroll
                for (int i = tid; i < 1024; i += 256) {
                    int r = i >> 3, g = i & 7;
                    uint32_t dst = S2B + stg + SMEM_SWIZZLE_128B((uint32_t)(r * 128 + g * 16));
                    cpa16(dst,         bkh + (size_t)(rb + r) * CDIM + g * 8);
                    cpa16(dst + 16384, bkl + (size_t)(rb + r) * CDIM + g * 8);
                }
                CP_COMMIT();
                CP_WAIT(1);
            } else {
                CP_WAIT(0);
            }
            __syncthreads();

            const uint32_t BH = S2B + (uint32_t)(nc & 1) * 32768;
            const uint32_t BL = BH + 16384;

            float tf[4][4][4];
            #pragma unroll
            for (int i = 0; i < 4; i++)
                #pragma unroll
                for (int j = 0; j < 4; j++)
                    #pragma unroll
                    for (int q = 0; q < 4; q++) tf[i][j][q] = 0.f;

            #pragma unroll
            for (int ks = 0; ks < 4; ks++) {
                const int ksb = ks * 32;
                uint32_t bh[4][2], bl[4][2];
                #pragma unroll
                for (int p = 0; p < 2; p++) {
                    uint32_t sw = SMEM_SWIZZLE_128B(
                        (uint32_t)((n_w + p * 16 + b_row) * 128 + ksb + b_kb));
                    uint32_t r4[4];
                    ldsm4(r4, BH + sw);
                    bh[2*p][0] = r4[0]; bh[2*p][1] = r4[1];
                    bh[2*p+1][0] = r4[2]; bh[2*p+1][1] = r4[3];
                    ldsm4(r4, BL + sw);
                    bl[2*p][0] = r4[0]; bl[2*p][1] = r4[1];
                    bl[2*p+1][0] = r4[2]; bl[2*p+1][1] = r4[3];
                }
                uint32_t ah[4][4], al[4][4];
                #pragma unroll
                for (int mt = 0; mt < 4; mt++) {
                    uint32_t sw = SMEM_SWIZZLE_128B(
                        (uint32_t)((m_w + mt * 16 + a_row) * 128 + ksb + a_kb));
                    ldsm4(ah[mt], QHI_U + sw);
                    ldsm4(al[mt], QLO_U + sw);
                }
                #pragma unroll
                for (int mt = 0; mt < 4; mt++)
                    #pragma unroll
                    for (int nt = 0; nt < 4; nt++) {
                        mma_bf16(tf[mt][nt], ah[mt], bh[nt]);
                        mma_bf16(tf[mt][nt], ah[mt], bl[nt]);
                        mma_bf16(tf[mt][nt], al[mt], bh[nt]);
                    }
            }

            #pragma unroll
            for (int mt = 0; mt < 4; mt++) {
                const int r = row0 + m_w + mt * 16 + (lane >> 2);
                #pragma unroll
                for (int nt = 0; nt < 4; nt++) {
                    const int c = nc * 128 + n_w + nt * 8 + (lane & 3) * 2;
                    *(float2*)(trow + (size_t)r * (NH * CDIM) + c) =
                        make_float2(tf[mt][nt][0], tf[mt][nt][1]);
                    *(float2*)(trow + (size_t)(r + 8) * (NH * CDIM) + c) =
                        make_float2(tf[mt][nt][2], tf[mt][nt][3]);
                }
            }
            __syncthreads();
        }
    }
}

// ---------------------------------------------------------------------------
// Fused per-(b,w), tensor-core edition (R12): t fp32 load+split; A planes out.
#define F4_XHI 0
#define F4_XLO 65536
#define F4_THI 131072
#define F4_TLO 163840
#define F4_SS  196608
#define F4_PTH 199680
#define F4_PTL 201728
#define F4_SMEM (203776 + 1024)

__global__ __launch_bounds__(1024)
void k_attn_fused4(const float* __restrict__ x) {
    extern __shared__ char fsm[];
    const uint32_t raw = smem_to_u32(fsm);
    const uint32_t padb = (1024u - (raw & 1023u)) & 1023u;
    char* base = fsm + padb;
    const uint32_t sb = raw + padb;

    char* xhi = base + F4_XHI;  char* xlo = base + F4_XLO;
    char* thi = base + F4_THI;  char* tlo = base + F4_TLO;
    float* Ssm = (float*)(base + F4_SS);
    char* pth = base + F4_PTH;  char* ptl = base + F4_PTL;
    const uint32_t XHI_U = sb + F4_XHI, XLO_U = sb + F4_XLO;
    const uint32_t THI_U = sb + F4_THI, TLO_U = sb + F4_TLO;
    const uint32_t PTH_U = sb + F4_PTH, PTL_U = sb + F4_PTL;

    const int bw   = blockIdx.x;
    const int tid  = threadIdx.x;
    const int wid  = tid >> 5, lane = tid & 31;
    const int last = g_last[bw];
    const float* xbase = x   + (size_t)bw * CSEQ * CDIM;
    const float* tbase = g_t + (size_t)bw * (NH * CDIM);

    {
        const int xr = tid >> 5, xg = (tid & 31) * 4;
        #pragma unroll
        for (int i = 0; i < 8; i++) {
            int c = xg + i * 128;
            float4 v = *(const float4*)(xbase + (size_t)xr * CDIM + c);
            int chunk = c >> 6;
            uint32_t sw = SMEM_SWIZZLE_128B((uint32_t)(xr * 128 + (c & 63) * 2));
            split_store(xhi + chunk * 4096, xlo + chunk * 4096, sw, v);
        }
        const int trr = tid >> 6, tg = (tid & 63) * 4;
        #pragma unroll
        for (int i = 0; i < 4; i++) {
            int c = tg + i * 256;
            float4 v = *(const float4*)(tbase + (size_t)trr * CDIM + c);
            int chunk = c >> 6;
            uint32_t sw = SMEM_SWIZZLE_128B((uint32_t)(trr * 128 + (c & 63) * 2));
            split_store(thi + chunk * 2048, tlo + chunk * 2048, sw, v);
        }
        if (tid < 544) Ssm[tid] = 0.f;
    }
    __syncthreads();

    {
        const int mt  = (wid >> 1) & 1;
        const int ntw = wid & 1;
        const int ks  = wid >> 2;
        float c4[4] = {0.f, 0.f, 0.f, 0.f};

        const int arow = (mt * 16 + (lane & 15)) * 128 + (lane >> 4) * 16;
        const int brow = ((lane & 7) + ((lane >> 4) & 1) * 8) * 128 + ((lane >> 3) & 1) * 16;

        #pragma unroll
        for (int cc = 0; cc < 2; cc++) {
            const int chunk = ks * 2 + cc;
            const uint32_t xb  = XHI_U + chunk * 4096, xbl = XLO_U + chunk * 4096;
            const uint32_t tb  = THI_U + chunk * 2048, tbl = TLO_U + chunk * 2048;
            #pragma unroll
            for (int kk = 0; kk < 4; kk++) {
                const int ksb = kk * 32;
                uint32_t ah[4], al[4], r4[4], r4l[4];
                ldsm4(ah, xb  + SMEM_SWIZZLE_128B((uint32_t)(arow + ksb)));
                ldsm4(al, xbl + SMEM_SWIZZLE_128B((uint32_t)(arow + ksb)));
                ldsm4(r4,  tb  + SMEM_SWIZZLE_128B((uint32_t)(brow + ksb)));
                ldsm4(r4l, tbl + SMEM_SWIZZLE_128B((uint32_t)(brow + ksb)));
                uint32_t bh[2] = {r4[2 * ntw],  r4[2 * ntw + 1]};
                uint32_t bl[2] = {r4l[2 * ntw], r4l[2 * ntw + 1]};
                mma_bf16(c4, ah, bh);
                mma_bf16(c4, ah, bl);
                mma_bf16(c4, al, bh);
            }
        }
        const int r0 = mt * 16 + (lane >> 2);
        const int c0 = ntw * 8 + (lane & 3) * 2;
        atomicAdd(&Ssm[r0 * 17 + c0],           c4[0]);
        atomicAdd(&Ssm[r0 * 17 + c0 + 1],       c4[1]);
        atomicAdd(&Ssm[(r0 + 8) * 17 + c0],     c4[2]);
        atomicAdd(&Ssm[(r0 + 8) * 17 + c0 + 1], c4[3]);
    }
    __syncthreads();

    if (tid < 512) {
        const int h = tid >> 5, j = lane;
        float s = (j <= last) ? Ssm[j * 17 + h] * 0.125f : -INFINITY;
        float m = s;
        #pragma unroll
        for (int off = 16; off; off >>= 1) m = fmaxf(m, __shfl_xor_sync(0xffffffffu, m, off));
        float e = (j <= last) ? __expf(s - m) : 0.f;
        float sum = e;
        #pragma unroll
        for (int off = 16; off; off >>= 1) sum += __shfl_xor_sync(0xffffffffu, sum, off);
        float p = e / sum;
        __nv_bfloat16 ph = __float2bfloat16(p);
        __nv_bfloat16 pl = __float2bfloat16(p - __bfloat162float(ph));
        uint32_t sw = SMEM_SWIZZLE_128B((uint32_t)(h * 128 + j * 2));
        *(__nv_bfloat16*)(pth + sw) = ph;
        *(__nv_bfloat16*)(ptl + sw) = pl;
    }
    __syncthreads();

    {
        const int cbase = wid * 32;
        uint32_t aPh[2][4], aPl[2][4];
        #pragma unroll
        for (int jt = 0; jt < 2; jt++) {
            uint32_t off = SMEM_SWIZZLE_128B((uint32_t)((lane & 15) * 128 + jt * 32 + (lane >> 4) * 16));
            ldsm4(aPh[jt], PTH_U + off);
            ldsm4(aPl[jt], PTL_U + off);
        }
        float c3[4][4];
        #pragma unroll
        for (int nt = 0; nt < 4; nt++)
            #pragma unroll
            for (int q = 0; q < 4; q++) c3[nt][q] = 0.f;

        #pragma unroll
        for (int ct = 0; ct < 2; ct++) {
            const int c0 = cbase + ct * 16;
            const int chunk = c0 >> 6, cin = c0 & 63;
            #pragma unroll
            for (int jt = 0; jt < 2; jt++) {
                const int jrow = (lane & 7) + ((lane >> 3) & 1) * 8 + jt * 16;
                uint32_t off = SMEM_SWIZZLE_128B(
                    (uint32_t)(jrow * 128 + (cin + ((lane >> 4) & 1) * 8) * 2));
                uint32_t bx[4], bxl[4];
                ldsm4t(bx,  XHI_U + chunk * 4096 + off);
                ldsm4t(bxl, XLO_U + chunk * 4096 + off);
                #pragma unroll
                for (int half = 0; half < 2; half++) {
                    const int nt = ct * 2 + half;
                    uint32_t bh[2] = {bx[2 * half],  bx[2 * half + 1]};
                    uint32_t bl[2] = {bxl[2 * half], bxl[2 * half + 1]};
                    mma_bf16(c3[nt], aPh[jt], bh);
                    mma_bf16(c3[nt], aPh[jt], bl);
                    mma_bf16(c3[nt], aPl[jt], bh);
                }
            }
        }
        __nv_bfloat16* Ahp = g_Ah + (size_t)bw * (NH * CDIM);
        __nv_bfloat16* Alp = g_Al + (size_t)bw * (NH * CDIM);
        #pragma unroll
        for (int nt = 0; nt < 4; nt++) {
            const int col = cbase + nt * 8 + (lane & 3) * 2;
            const int r = lane >> 2;
            __nv_bfloat16 h0, l0, h1, l1;
            split1(c3[nt][0], &h0, &l0);
            split1(c3[nt][1], &h1, &l1);
            *(uint32_t*)(Ahp + (size_t)r * CDIM + col) = pkbf(h0, h1);
            *(uint32_t*)(Alp + (size_t)r * CDIM + col) = pkbf(l0, l1);
            split1(c3[nt][2], &h0, &l0);
            split1(c3[nt][3], &h1, &l1);
            *(uint32_t*)(Ahp + (size_t)(r + 8) * CDIM + col) = pkbf(h0, h1);
            *(uint32_t*)(Alp + (size_t)(r + 8) * CDIM + col) = pkbf(l0, l1);
        }
    }
}

// ---------------------------------------------------------------------------
// O GEMM: MTILE=128, NTILE=64, 1024 threads (32 warps: 8m x 4n), grid (1,8,NH).
#define OG_A 0
#define OG_B 65536
#define OG_SMEM (98304 + 1024)

__global__ __launch_bounds__(1024)
void k_ogemm_pp(const float* __restrict__ pos) {
    extern __shared__ char dsm[];
    const uint32_t raw = smem_to_u32(dsm);
    const uint32_t padb = (1024u - (raw & 1023u)) & 1023u;
    const uint32_t sb = raw + padb;
    const uint32_t A_BASE = sb + OG_A;
    const uint32_t B_BASE = sb + OG_B;

    const int tid = threadIdx.x, wid = tid >> 5, lane = tid & 31;
    const int row0 = blockIdx.y * 128;
    const int hz = blockIdx.z;

    const int m_w = (wid >> 2) * 16;      // 8 m-tiles of 16
    const int n_w = (wid & 3) * 16;       // 4 n-tiles of 16

    const int a_row = lane & 15;
    const int a_kb  = (lane >> 4) * 16;
    const int b_row = (lane & 7) + ((lane >> 4) * 8);
    const int b_kb  = ((lane >> 3) & 1) * 16;

    const __nv_bfloat16* Ahp = g_Ah + (size_t)hz * CDIM;
    const __nv_bfloat16* Alp = g_Al + (size_t)hz * CDIM;
    const __nv_bfloat16* Bhp = g_Wh + 2 * (size_t)CDIM * CDIM + (size_t)hz * HD * CDIM;
    const __nv_bfloat16* Blp = g_Wl + 2 * (size_t)CDIM * CDIM + (size_t)hz * HD * CDIM;

    float cfr[2][4];
    #pragma unroll
    for (int j = 0; j < 2; j++)
        #pragma unroll
        for (int q = 0; q < 4; q++) cfr[j][q] = 0.f;

    // prologue: A 1024 slots (one per thread), B 512 slots (tid<512)
    {
        int r = tid >> 3, g = tid & 7;
        uint32_t dst = A_BASE + SMEM_SWIZZLE_128B((uint32_t)(r * 128 + g * 16));
        cpa16(dst,         Ahp + (size_t)(row0 + r) * (NH * CDIM) + g * 8);
        cpa16(dst + 16384, Alp + (size_t)(row0 + r) * (NH * CDIM) + g * 8);
    }
    if (tid < 512) {
        int r = tid >> 3, g = tid & 7;
        uint32_t dst = B_BASE + SMEM_SWIZZLE_128B((uint32_t)(r * 128 + g * 16));
        cpa16(dst,        Bhp + (size_t)r * CDIM + g * 8);
        cpa16(dst + 8192, Blp + (size_t)r * CDIM + g * 8);
    }
    CP_COMMIT();

    for (int ch = 0; ch < 16; ch++) {
        if (ch + 1 < 16) {
            const uint32_t astg = (uint32_t)((ch + 1) & 1) * 32768;
            const uint32_t bstg = (uint32_t)((ch + 1) & 1) * 16384;
            const int kb = (ch + 1) * 64;
            {
                int r = tid >> 3, g = tid & 7;
                uint32_t dst = A_BASE + astg + SMEM_SWIZZLE_128B((uint32_t)(r * 128 + g * 16));
                cpa16(dst,         Ahp + (size_t)(row0 + r) * (NH * CDIM) + kb + g * 8);
                cpa16(dst + 16384, Alp + (size_t)(row0 + r) * (NH * CDIM) + kb + g * 8);
            }
            if (tid < 512) {
                int r = tid >> 3, g = tid & 7;
                uint32_t dst = B_BASE + bstg + SMEM_SWIZZLE_128B((uint32_t)(r * 128 + g * 16));
                cpa16(dst,        Bhp + (size_t)r * CDIM + kb + g * 8);
                cpa16(dst + 8192, Blp + (size_t)r * CDIM + kb + g * 8);
            }
            CP_COMMIT();
            CP_WAIT(1);
        } else {
            CP_WAIT(0);
        }
        __syncthreads();

        const uint32_t AH = A_BASE + (uint32_t)(ch & 1) * 32768;
        const uint32_t AL = AH + 16384;
        const uint32_t BH = B_BASE + (uint32_t)(ch & 1) * 16384;
        const uint32_t BL = BH + 8192;

        #pragma unroll
        for (int ks = 0; ks < 4; ks++) {
            const int ksb = ks * 32;
            uint32_t bh[2][2], bl[2][2];
            {
                uint32_t sw = SMEM_SWIZZLE_128B(
                    (uint32_t)((n_w + b_row) * 128 + ksb + b_kb));
                uint32_t r4[4];
                ldsm4(r4, BH + sw);
                bh[0][0] = r4[0]; bh[0][1] = r4[1];
                bh[1][0] = r4[2]; bh[1][1] = r4[3];
                ldsm4(r4, BL + sw);
                bl[0][0] = r4[0]; bl[0][1] = r4[1];
                bl[1][0] = r4[2]; bl[1][1] = r4[3];
            }
            uint32_t ah[4], al[4];
            {
                uint32_t sw = SMEM_SWIZZLE_128B(
                    (uint32_t)((m_w + a_row) * 128 + ksb + a_kb));
                ldsm4(ah, AH + sw);
                ldsm4(al, AL + sw);
            }
            #pragma unroll
            for (int nt = 0; nt < 2; nt++) {
                mma_bf16(cfr[nt], ah, bh[nt]);
                mma_bf16(cfr[nt], ah, bl[nt]);
                mma_bf16(cfr[nt], al, bh[nt]);
            }
        }
        __syncthreads();
    }

    // epilogue: add pos, split, write g_oh/g_ol
    #pragma unroll
    for (int nt = 0; nt < 2; nt++) {
        const int cg = hz * HD + n_w + nt * 8 + (lane & 3) * 2;
        #pragma unroll
        for (int half = 0; half < 2; half++) {
            const int r = row0 + m_w + (lane >> 2) + half * 8;
            const float* pr = pos + (size_t)(r & (WW - 1)) * CDIM + cg;
            float v0 = cfr[nt][half * 2]     + pr[0];
            float v1 = cfr[nt][half * 2 + 1] + pr[1];
            __nv_bfloat16 h0, l0, h1, l1;
            split1(v0, &h0, &l0);
            split1(v1, &h1, &l1);
            *(uint32_t*)(g_oh + (size_t)r * CDIM + cg) = pkbf(h0, h1);
            *(uint32_t*)(g_ol + (size_t)r * CDIM + cg) = pkbf(l0, l1);
        }
    }
}

// ---------------------------------------------------------------------------
// Proj GEMM: MTILE=64, NTILE=128, 1024 threads (32 warps: 4m x 8n), grid (8,16).
#define PJ_A 0
#define PJ_B 32768
#define PJ_SMEM (98304 + 1024)

__global__ __launch_bounds__(1024)
void k_proj_pp(float* __restrict__ out) {
    extern __shared__ char dsm[];
    const uint32_t raw = smem_to_u32(dsm);
    const uint32_t padb = (1024u - (raw & 1023u)) & 1023u;
    const uint32_t sb = raw + padb;
    const uint32_t A_BASE = sb + PJ_A;
    const uint32_t B_BASE = sb + PJ_B;

    const int tid = threadIdx.x, wid = tid >> 5, lane = tid & 31;
    const int row0 = blockIdx.y * 64;
    const int col0 = blockIdx.x * 128;

    const int m_w = (wid >> 3) * 16;      // 4 m-tiles of 16
    const int n_w = (wid & 7) * 16;       // 8 n-tiles of 16

    const int a_row = lane & 15;
    const int a_kb  = (lane >> 4) * 16;
    const int b_row = (lane & 7) + ((lane >> 4) * 8);
    const int b_kb  = ((lane >> 3) & 1) * 16;

    const __nv_bfloat16* Bhp = g_Wh + (size_t)CDIM * CDIM;
    const __nv_bfloat16* Blp = g_Wl + (size_t)CDIM * CDIM;

    float cfr[2][4];
    #pragma unroll
    for (int j = 0; j < 2; j++)
        #pragma unroll
        for (int q = 0; q < 4; q++) cfr[j][q] = 0.f;

    // prologue: A 512 slots (tid<512), B 1024 slots (one per thread)
    if (tid < 512) {
        int r = tid >> 3, g = tid & 7;
        uint32_t dst = A_BASE + SMEM_SWIZZLE_128B((uint32_t)(r * 128 + g * 16));
        cpa16(dst,        g_oh + (size_t)(row0 + r) * CDIM + g * 8);
        cpa16(dst + 8192, g_ol + (size_t)(row0 + r) * CDIM + g * 8);
    }
    {
        int r = tid >> 3, g = tid & 7;
        uint32_t dst = B_BASE + SMEM_SWIZZLE_128B((uint32_t)(r * 128 + g * 16));
        cpa16(dst,         Bhp + (size_t)(col0 + r) * CDIM + g * 8);
        cpa16(dst + 16384, Blp + (size_t)(col0 + r) * CDIM + g * 8);
    }
    CP_COMMIT();

    for (int ch = 0; ch < 16; ch++) {
        if (ch + 1 < 16) {
            const uint32_t astg = (uint32_t)((ch + 1) & 1) * 16384;
            const uint32_t bstg = (uint32_t)((ch + 1) & 1) * 32768;
            const int kb = (ch + 1) * 64;
            if (tid < 512) {
                int r = tid >> 3, g = tid & 7;
                uint32_t dst = A_BASE + astg + SMEM_SWIZZLE_128B((uint32_t)(r * 128 + g * 16));
                cpa16(dst,        g_oh + (size_t)(row0 + r) * CDIM + kb + g * 8);
                cpa16(dst + 8192, g_ol + (size_t)(row0 + r) * CDIM + kb + g * 8);
            }
            {
                int r = tid >> 3, g = tid & 7;
                uint32_t dst = B_BASE + bstg + SMEM_SWIZZLE_128B((uint32_t)(r * 128 + g * 16));
                cpa16(dst,         Bhp + (size_t)(col0 + r) * CDIM + kb + g * 8);
                cpa16(dst + 16384, Blp + (size_t)(col0 + r) * CDIM + kb + g * 8);
            }
            CP_COMMIT();
            CP_WAIT(1);
        } else {
            CP_WAIT(0);
        }
        __syncthreads();

        const uint32_t AH = A_BASE + (uint32_t)(ch & 1) * 16384;
        const uint32_t AL = AH + 8192;
        const uint32_t BH = B_BASE + (uint32_t)(ch & 1) * 32768;
        const uint32_t BL = BH + 16384;

        #pragma unroll
        for (int ks = 0; ks < 4; ks++) {
            const int ksb = ks * 32;
            uint32_t bh[2][2], bl[2][2];
            {
                uint32_t sw = SMEM_SWIZZLE_128B(
                    (uint32_t)((n_w + b_row) * 128 + ksb + b_kb));
                uint32_t r4[4];
                ldsm4(r4, BH + sw);
                bh[0][0] = r4[0]; bh[0][1] = r4[1];
                bh[1][0] = r4[2]; bh[1][1] = r4[3];
                ldsm4(r4, BL + sw);
                bl[0][0] = r4[0]; bl[0][1] = r4[1];
                bl[1][0] = r4[2]; bl[1][1] = r4[3];
            }
            uint32_t ah[4], al[4];
            {
                uint32_t sw = SMEM_SWIZZLE_128B(
                    (uint32_t)((m_w + a_row) * 128 + ksb + a_kb));
                ldsm4(ah, AH + sw);
                ldsm4(al, AL + sw);
            }
            #pragma unroll
            for (int nt = 0; nt < 2; nt++) {
                mma_bf16(cfr[nt], ah, bh[nt]);
                mma_bf16(cfr[nt], ah, bl[nt]);
                mma_bf16(cfr[nt], al, bh[nt]);
            }
        }
        __syncthreads();
    }

    {
        int r0 = row0 + m_w + (lane >> 2);
        #pragma unroll
        for (int nt = 0; nt < 2; nt++) {
            int c0 = col0 + n_w + nt * 8 + (lane & 3) * 2;
            *(float2*)(out + (size_t)r0 * CDIM + c0) = make_float2(cfr[nt][0], cfr[nt][1]);
            *(float2*)(out + (size_t)(r0 + 8) * CDIM + c0) = make_float2(cfr[nt][2], cfr[nt][3]);
        }
    }
}

// ---------------------------------------------------------------------------
extern "C" void kernel_launch(void* const* d_in, const int* in_sizes, int n_in,
                              void* d_out, int out_size) {
    const float* x      = (const float*)d_in[0];  // (4,256,32,1024)
    const int*   mask   = (const int*)  d_in[1];  // (4,256,32)
    const float* pos    = (const float*)d_in[2];  // (256,1024)
    const float* attn_w = (const float*)d_in[3];  // (1024,3072)
    const float* proj_w = (const float*)d_in[4];  // (1024,1024)
    float*       out    = (float*)d_out;          // (4,256,1024)

    __nv_bfloat16 *wh, *wl;
    cudaGetSymbolAddress((void**)&wh, g_Wh);
    cudaGetSymbolAddress((void**)&wl, g_Wl);
    const size_t WSZ = (size_t)CDIM * CDIM;

    static int attr_set = 0;
    if (!attr_set) {
        cudaFuncSetAttribute(k_attn_fused4, cudaFuncAttributeMaxDynamicSharedMemorySize, F4_SMEM);
        cudaFuncSetAttribute(k_qt, cudaFuncAttributeMaxDynamicSharedMemorySize, QT_SMEM);
        cudaFuncSetAttribute(k_ogemm_pp, cudaFuncAttributeMaxDynamicSharedMemorySize, OG_SMEM);
        cudaFuncSetAttribute(k_proj_pp, cudaFuncAttributeMaxDynamicSharedMemorySize, PJ_SMEM);
        attr_set = 1;
    }

    // 1) prep: weight splits (4 jobs) + g_last
    {
        dim3 grid(32, 32, 5), blk(32, 8);
        k_prep<<<grid, blk>>>(attn_w, proj_w, mask);
    }

    // 2) fused Q + t (256 threads, R12) -> t fp32
    {
        dim3 grid(1, 8, NH);
        k_qt<<<grid, 256, QT_SMEM>>>(x, wh, wl, wh + 3 * WSZ, wl + 3 * WSZ);
    }

    // 3) fused scores + softmax + mix -> A bf16 planes
    k_attn_fused4<<<BW, 1024, F4_SMEM>>>(x);

    // 4) O = A_h @ Wv_h + pos -> bf16 planes  (1024 threads, 32 warps)
    {
        dim3 grid(1, 8, NH);
        k_ogemm_pp<<<grid, 1024, OG_SMEM>>>(pos);
    }

    // 5) out = O+ @ proj^T  (1024 threads, 32 warps)
    {
        dim3 grid(8, 16, 1);
        k_proj_pp<<<grid, 1024, PJ_SMEM>>>(out);
    }
}

// round 17
// speedup vs baseline: 1.0417x; 1.0417x over previous
#include <cuda_runtime.h>
#include <cuda_bf16.h>
#include <cstdint>
#include <math.h>

#define BB   4
#define WW   256
#define CSEQ 32
#define CDIM 1024
#define NH   16
#define HD   64
#define BW   1024

typedef unsigned long long ull;

// Scratch (device globals: allocation-free rule)
__device__ float g_t [(size_t)BW * NH * CDIM];
__device__ __nv_bfloat16 g_Ah[(size_t)BW * NH * CDIM];
__device__ __nv_bfloat16 g_Al[(size_t)BW * NH * CDIM];
__device__ __nv_bfloat16 g_oh[(size_t)BW * CDIM];
__device__ __nv_bfloat16 g_ol[(size_t)BW * CDIM];
// pre-split weight planes: [0]=Wq^T, [1]=proj^T, [2]=Wv^T, [3]=Wk  (each [1024][1024])
__device__ __nv_bfloat16 g_Wh[4 * (size_t)CDIM * CDIM];
__device__ __nv_bfloat16 g_Wl[4 * (size_t)CDIM * CDIM];
__device__ int g_last[BW];

// ===========================================================================
__device__ __forceinline__ uint32_t smem_to_u32(const void* smem_ptr) {
    uint32_t addr;
    asm("{ .reg .u64 tmp; cvta.to.shared.u64 tmp, %1; cvt.u32.u64 %0, tmp; }"
        : "=r"(addr) : "l"(smem_ptr));
    return addr;
}
#define SMEM_SWIZZLE_128B(byte_offset) ((byte_offset) ^ (((byte_offset) >> 3) & 0x70))

__device__ __forceinline__ void mma_bf16(float* d, const uint32_t* a, const uint32_t* b) {
    asm volatile(
        "mma.sync.aligned.m16n8k16.row.col.f32.bf16.bf16.f32 "
        "{%0,%1,%2,%3}, {%4,%5,%6,%7}, {%8,%9}, {%0,%1,%2,%3};"
        : "+f"(d[0]), "+f"(d[1]), "+f"(d[2]), "+f"(d[3])
        : "r"(a[0]), "r"(a[1]), "r"(a[2]), "r"(a[3]), "r"(b[0]), "r"(b[1]));
}
__device__ __forceinline__ void ldsm4(uint32_t* r, uint32_t addr) {
    asm volatile("ldmatrix.sync.aligned.m8n8.x4.shared.b16 {%0,%1,%2,%3}, [%4];"
        : "=r"(r[0]), "=r"(r[1]), "=r"(r[2]), "=r"(r[3]) : "r"(addr));
}
__device__ __forceinline__ void ldsm4t(uint32_t* r, uint32_t addr) {
    asm volatile("ldmatrix.sync.aligned.m8n8.x4.trans.shared.b16 {%0,%1,%2,%3}, [%4];"
        : "=r"(r[0]), "=r"(r[1]), "=r"(r[2]), "=r"(r[3]) : "r"(addr));
}
__device__ __forceinline__ void cpa16(uint32_t dst, const void* src) {
    asm volatile("cp.async.cg.shared.global [%0], [%1], 16;" :: "r"(dst), "l"(src));
}
#define CP_COMMIT()  asm volatile("cp.async.commit_group;" ::: "memory")
#define CP_WAIT(n)   asm volatile("cp.async.wait_group %0;" :: "n"(n) : "memory")

// bf16 hi/lo split helpers
__device__ __forceinline__ uint32_t pkbf(__nv_bfloat16 a, __nv_bfloat16 b) {
    return (uint32_t)__bfloat16_as_ushort(a) | ((uint32_t)__bfloat16_as_ushort(b) << 16);
}
__device__ __forceinline__ void split_store(char* hi, char* lo, uint32_t sw, float4 v) {
    __nv_bfloat16 a0 = __float2bfloat16(v.x), a1 = __float2bfloat16(v.y),
                  a2 = __float2bfloat16(v.z), a3 = __float2bfloat16(v.w);
    float r0 = v.x - __bfloat162float(a0), r1 = v.y - __bfloat162float(a1),
          r2 = v.z - __bfloat162float(a2), r3 = v.w - __bfloat162float(a3);
    __nv_bfloat16 b0 = __float2bfloat16(r0), b1 = __float2bfloat16(r1),
                  b2 = __float2bfloat16(r2), b3 = __float2bfloat16(r3);
    *(uint2*)(hi + sw) = make_uint2(pkbf(a0, a1), pkbf(a2, a3));
    *(uint2*)(lo + sw) = make_uint2(pkbf(b0, b1), pkbf(b2, b3));
}
__device__ __forceinline__ void split1(float v, __nv_bfloat16* hi, __nv_bfloat16* lo) {
    __nv_bfloat16 h = __float2bfloat16(v);
    *hi = h;
    *lo = __float2bfloat16(v - __bfloat162float(h));
}

// ---------------------------------------------------------------------------
// Prep: z=0..2 transpose+split (Wq^T, proj^T, Wv^T), z=3 copy+split Wk, z=4 g_last.
__global__ __launch_bounds__(256)
void k_prep(const float* __restrict__ attn_w, const float* __restrict__ proj_w,
            const int* __restrict__ mask) {
    const int z = blockIdx.z;
    const int tx = threadIdx.x, ty = threadIdx.y;
    if (z == 4) {
        if (blockIdx.y == 0 && blockIdx.x < 4) {
            int i = blockIdx.x * 256 + ty * 32 + tx;
            int s = 0;
            #pragma unroll
            for (int j = 0; j < CSEQ; j++) s += mask[i * CSEQ + j];
            g_last[i] = s - 1;
        }
        return;
    }
    if (z == 3) {
        const int n0 = blockIdx.y * 32, k0 = blockIdx.x * 32;
        __nv_bfloat16* oh = g_Wh + 3 * (size_t)CDIM * CDIM;
        __nv_bfloat16* ol = g_Wl + 3 * (size_t)CDIM * CDIM;
        #pragma unroll
        for (int i = ty; i < 32; i += 8) {
            float v = attn_w[(size_t)(n0 + i) * 3072 + CDIM + k0 + tx];
            split1(v, oh + (size_t)(n0 + i) * CDIM + k0 + tx,
                      ol + (size_t)(n0 + i) * CDIM + k0 + tx);
        }
        return;
    }
    const float* in; int ldin;
    if (z == 0)      { in = attn_w;            ldin = 3 * CDIM; }
    else if (z == 1) { in = proj_w;            ldin = CDIM; }
    else             { in = attn_w + 2 * CDIM; ldin = 3 * CDIM; }
    __nv_bfloat16* oh = g_Wh + (size_t)z * CDIM * CDIM;
    __nv_bfloat16* ol = g_Wl + (size_t)z * CDIM * CDIM;

    __shared__ float t[32][33];
    const int k0 = blockIdx.y * 32, n0 = blockIdx.x * 32;
    #pragma unroll
    for (int i = ty; i < 32; i += 8)
        t[i][tx] = in[(size_t)(k0 + i) * ldin + n0 + tx];
    __syncthreads();
    #pragma unroll
    for (int i = ty; i < 32; i += 8) {
        float v = t[tx][i];
        split1(v, oh + (size_t)(n0 + i) * CDIM + k0 + tx,
                  ol + (size_t)(n0 + i) * CDIM + k0 + tx);
    }
}

// ---------------------------------------------------------------------------
// Fused Q+t kernel (R12, 256 threads). grid (1, 8, 16). t out: fp32.
#define QT_QHI 0
#define QT_QLO 16384
#define QT_A   32768
#define QT_S1B 65536
#define QT_S2B 98304
#define QT_SMEM (163840 + 1024)

__global__ __launch_bounds__(256)
void k_qt(const float* __restrict__ x,
          const __nv_bfloat16* __restrict__ Wqh, const __nv_bfloat16* __restrict__ Wql,
          const __nv_bfloat16* __restrict__ Wkh, const __nv_bfloat16* __restrict__ Wkl) {
    extern __shared__ char dsm[];
    const uint32_t raw = smem_to_u32(dsm);
    const uint32_t padb = (1024u - (raw & 1023u)) & 1023u;
    char* base = dsm + padb;
    const uint32_t sb = raw + padb;

    char* qhi = base + QT_QHI;
    char* qlo = base + QT_QLO;
    char* a_hi = base + QT_A;
    char* a_lo = base + QT_A + 16384;
    const uint32_t QHI_U = sb + QT_QHI, QLO_U = sb + QT_QLO;
    const uint32_t A_HI = sb + QT_A, A_LO = sb + QT_A + 16384;
    const uint32_t S1B = sb + QT_S1B;
    const uint32_t S2B = sb + QT_S2B;

    const int tid = threadIdx.x, wid = tid >> 5, lane = tid & 31;
    const int row0 = blockIdx.y * 128;
    const int h = blockIdx.z;

    const int a_row = lane & 15;
    const int a_kb  = (lane >> 4) * 16;
    const int b_row = (lane & 7) + ((lane >> 4) * 8);
    const int b_kb  = ((lane >> 3) & 1) * 16;

    // stage 1: q = gather(x) @ Wq_h
    {
        const int m_w = (wid >> 1) * 32;
        const int n_w = (wid & 1) * 32;
        float q4[2][4][4];
        #pragma unroll
        for (int i = 0; i < 2; i++)
            #pragma unroll
            for (int j = 0; j < 4; j++)
                #pragma unroll
                for (int q = 0; q < 4; q++) q4[i][j][q] = 0.f;

        const float* aptr[8];
        uint32_t aswz[8];
        #pragma unroll
        for (int i = 0; i < 8; i++) {
            int s = tid + i * 256;
            int r = s >> 4, kq = (s & 15) * 4;
            int grow = row0 + r;
            aptr[i] = x + ((size_t)grow * CSEQ + g_last[grow]) * CDIM + kq;
            aswz[i] = SMEM_SWIZZLE_128B((uint32_t)(r * 128 + kq * 2));
        }

        const __nv_bfloat16* bqh = Wqh + (size_t)h * HD * CDIM;
        const __nv_bfloat16* bql = Wql + (size_t)h * HD * CDIM;

        #pragma unroll
        for (int i = tid; i < 512; i += 256) {
            int r = i >> 3, g = i & 7;
            uint32_t dst = S1B + SMEM_SWIZZLE_128B((uint32_t)(r * 128 + g * 16));
            cpa16(dst,        bqh + (size_t)r * CDIM + g * 8);
            cpa16(dst + 8192, bql + (size_t)r * CDIM + g * 8);
        }
        CP_COMMIT();

        float4 ra[8];
        #pragma unroll
        for (int i = 0; i < 8; i++) ra[i] = *(const float4*)(aptr[i]);

        for (int ch = 0; ch < 16; ch++) {
            #pragma unroll
            for (int i = 0; i < 8; i++) split_store(a_hi, a_lo, aswz[i], ra[i]);

            if (ch + 1 < 16) {
                const uint32_t stg = (uint32_t)((ch + 1) & 1) * 16384;
                const int kb = (ch + 1) * 64;
                #pragma unroll
                for (int i = tid; i < 512; i += 256) {
                    int r = i >> 3, g = i & 7;
                    uint32_t dst = S1B + stg + SMEM_SWIZZLE_128B((uint32_t)(r * 128 + g * 16));
                    cpa16(dst,        bqh + (size_t)r * CDIM + kb + g * 8);
                    cpa16(dst + 8192, bql + (size_t)r * CDIM + kb + g * 8);
                }
                CP_COMMIT();
                CP_WAIT(1);
            } else {
                CP_WAIT(0);
            }
            __syncthreads();

            if (ch + 1 < 16) {
                const int kb = (ch + 1) << 6;
                #pragma unroll
                for (int i = 0; i < 8; i++) ra[i] = *(const float4*)(aptr[i] + kb);
            }

            const uint32_t BH = S1B + (uint32_t)(ch & 1) * 16384;
            const uint32_t BL = BH + 8192;

            #pragma unroll
            for (int ks = 0; ks < 4; ks++) {
                const int ksb = ks * 32;
                uint32_t bh[4][2], bl[4][2];
                #pragma unroll
                for (int p = 0; p < 2; p++) {
                    uint32_t sw = SMEM_SWIZZLE_128B(
                        (uint32_t)((n_w + p * 16 + b_row) * 128 + ksb + b_kb));
                    uint32_t r4[4];
                    ldsm4(r4, BH + sw);
                    bh[2*p][0] = r4[0]; bh[2*p][1] = r4[1];
                    bh[2*p+1][0] = r4[2]; bh[2*p+1][1] = r4[3];
                    ldsm4(r4, BL + sw);
                    bl[2*p][0] = r4[0]; bl[2*p][1] = r4[1];
                    bl[2*p+1][0] = r4[2]; bl[2*p+1][1] = r4[3];
                }
                uint32_t ah[2][4], al[2][4];
                #pragma unroll
                for (int mt = 0; mt < 2; mt++) {
                    uint32_t sw = SMEM_SWIZZLE_128B(
                        (uint32_t)((m_w + mt * 16 + a_row) * 128 + ksb + a_kb));
                    ldsm4(ah[mt], A_HI + sw);
                    ldsm4(al[mt], A_LO + sw);
                }
                #pragma unroll
                for (int mt = 0; mt < 2; mt++)
                    #pragma unroll
                    for (int nt = 0; nt < 4; nt++) {
                        mma_bf16(q4[mt][nt], ah[mt], bh[nt]);
                        mma_bf16(q4[mt][nt], ah[mt], bl[nt]);
                        mma_bf16(q4[mt][nt], al[mt], bh[nt]);
                    }
            }
            __syncthreads();
        }

        #pragma unroll
        for (int mt = 0; mt < 2; mt++) {
            const int r0 = m_w + mt * 16 + (lane >> 2);
            #pragma unroll
            for (int nt = 0; nt < 4; nt++) {
                const int c0 = n_w + nt * 8 + (lane & 3) * 2;
                __nv_bfloat16 h0, l0, h1, l1;
                split1(q4[mt][nt][0], &h0, &l0);
                split1(q4[mt][nt][1], &h1, &l1);
                uint32_t sw = SMEM_SWIZZLE_128B((uint32_t)(r0 * 128 + c0 * 2));
                *(uint32_t*)(qhi + sw) = pkbf(h0, h1);
                *(uint32_t*)(qlo + sw) = pkbf(l0, l1);
                split1(q4[mt][nt][2], &h0, &l0);
                split1(q4[mt][nt][3], &h1, &l1);
                sw = SMEM_SWIZZLE_128B((uint32_t)((r0 + 8) * 128 + c0 * 2));
                *(uint32_t*)(qhi + sw) = pkbf(h0, h1);
                *(uint32_t*)(qlo + sw) = pkbf(l0, l1);
            }
        }
    }
    __syncthreads();

    // stage 2: t = q @ Wk_h^T
    {
        const int m_w = (wid >> 2) * 64;
        const int n_w = (wid & 3) * 32;
        const __nv_bfloat16* bkh = Wkh + (size_t)h * HD;
        const __nv_bfloat16* bkl = Wkl + (size_t)h * HD;

        #pragma unroll
        for (int i = tid; i < 1024; i += 256) {
            int r = i >> 3, g = i & 7;
            uint32_t dst = S2B + SMEM_SWIZZLE_128B((uint32_t)(r * 128 + g * 16));
            cpa16(dst,         bkh + (size_t)r * CDIM + g * 8);
            cpa16(dst + 16384, bkl + (size_t)r * CDIM + g * 8);
        }
        CP_COMMIT();

        float* trow = g_t + (size_t)h * CDIM;

        for (int nc = 0; nc < 8; nc++) {
            if (nc + 1 < 8) {
                const uint32_t stg = (uint32_t)((nc + 1) & 1) * 32768;
                const int rb = (nc + 1) * 128;
                #pragma unroll
                for (int i = tid; i < 1024; i += 256) {
                    int r = i >> 3, g = i & 7;
                    uint32_t dst = S2B + stg + SMEM_SWIZZLE_128B((uint32_t)(r * 128 + g * 16));
                    cpa16(dst,         bkh + (size_t)(rb + r) * CDIM + g * 8);
                    cpa16(dst + 16384, bkl + (size_t)(rb + r) * CDIM + g * 8);
                }
                CP_COMMIT();
                CP_WAIT(1);
            } else {
                CP_WAIT(0);
            }
            __syncthreads();

            const uint32_t BH = S2B + (uint32_t)(nc & 1) * 32768;
            const uint32_t BL = BH + 16384;

            float tf[4][4][4];
            #pragma unroll
            for (int i = 0; i < 4; i++)
                #pragma unroll
                for (int j = 0; j < 4; j++)
                    #pragma unroll
                    for (int q = 0; q < 4; q++) tf[i][j][q] = 0.f;

            #pragma unroll
            for (int ks = 0; ks < 4; ks++) {
                const int ksb = ks * 32;
                uint32_t bh[4][2], bl[4][2];
                #pragma unroll
                for (int p = 0; p < 2; p++) {
                    uint32_t sw = SMEM_SWIZZLE_128B(
                        (uint32_t)((n_w + p * 16 + b_row) * 128 + ksb + b_kb));
                    uint32_t r4[4];
                    ldsm4(r4, BH + sw);
                    bh[2*p][0] = r4[0]; bh[2*p][1] = r4[1];
                    bh[2*p+1][0] = r4[2]; bh[2*p+1][1] = r4[3];
                    ldsm4(r4, BL + sw);
                    bl[2*p][0] = r4[0]; bl[2*p][1] = r4[1];
                    bl[2*p+1][0] = r4[2]; bl[2*p+1][1] = r4[3];
                }
                uint32_t ah[4][4], al[4][4];
                #pragma unroll
                for (int mt = 0; mt < 4; mt++) {
                    uint32_t sw = SMEM_SWIZZLE_128B(
                        (uint32_t)((m_w + mt * 16 + a_row) * 128 + ksb + a_kb));
                    ldsm4(ah[mt], QHI_U + sw);
                    ldsm4(al[mt], QLO_U + sw);
                }
                #pragma unroll
                for (int mt = 0; mt < 4; mt++)
                    #pragma unroll
                    for (int nt = 0; nt < 4; nt++) {
                        mma_bf16(tf[mt][nt], ah[mt], bh[nt]);
                        mma_bf16(tf[mt][nt], ah[mt], bl[nt]);
                        mma_bf16(tf[mt][nt], al[mt], bh[nt]);
                    }
            }

            #pragma unroll
            for (int mt = 0; mt < 4; mt++) {
                const int r = row0 + m_w + mt * 16 + (lane >> 2);
                #pragma unroll
                for (int nt = 0; nt < 4; nt++) {
                    const int c = nc * 128 + n_w + nt * 8 + (lane & 3) * 2;
                    *(float2*)(trow + (size_t)r * (NH * CDIM) + c) =
                        make_float2(tf[mt][nt][0], tf[mt][nt][1]);
                    *(float2*)(trow + (size_t)(r + 8) * (NH * CDIM) + c) =
                        make_float2(tf[mt][nt][2], tf[mt][nt][3]);
                }
            }
            __syncthreads();
        }
    }
}

// ---------------------------------------------------------------------------
// Fused per-(b,w), tensor-core edition (R12): t fp32 load+split; A planes out.
#define F4_XHI 0
#define F4_XLO 65536
#define F4_THI 131072
#define F4_TLO 163840
#define F4_SS  196608
#define F4_PTH 199680
#define F4_PTL 201728
#define F4_SMEM (203776 + 1024)

__global__ __launch_bounds__(1024)
void k_attn_fused4(const float* __restrict__ x) {
    extern __shared__ char fsm[];
    const uint32_t raw = smem_to_u32(fsm);
    const uint32_t padb = (1024u - (raw & 1023u)) & 1023u;
    char* base = fsm + padb;
    const uint32_t sb = raw + padb;

    char* xhi = base + F4_XHI;  char* xlo = base + F4_XLO;
    char* thi = base + F4_THI;  char* tlo = base + F4_TLO;
    float* Ssm = (float*)(base + F4_SS);
    char* pth = base + F4_PTH;  char* ptl = base + F4_PTL;
    const uint32_t XHI_U = sb + F4_XHI, XLO_U = sb + F4_XLO;
    const uint32_t THI_U = sb + F4_THI, TLO_U = sb + F4_TLO;
    const uint32_t PTH_U = sb + F4_PTH, PTL_U = sb + F4_PTL;

    const int bw   = blockIdx.x;
    const int tid  = threadIdx.x;
    const int wid  = tid >> 5, lane = tid & 31;
    const int last = g_last[bw];
    const float* xbase = x   + (size_t)bw * CSEQ * CDIM;
    const float* tbase = g_t + (size_t)bw * (NH * CDIM);

    {
        const int xr = tid >> 5, xg = (tid & 31) * 4;
        #pragma unroll
        for (int i = 0; i < 8; i++) {
            int c = xg + i * 128;
            float4 v = *(const float4*)(xbase + (size_t)xr * CDIM + c);
            int chunk = c >> 6;
            uint32_t sw = SMEM_SWIZZLE_128B((uint32_t)(xr * 128 + (c & 63) * 2));
            split_store(xhi + chunk * 4096, xlo + chunk * 4096, sw, v);
        }
        const int trr = tid >> 6, tg = (tid & 63) * 4;
        #pragma unroll
        for (int i = 0; i < 4; i++) {
            int c = tg + i * 256;
            float4 v = *(const float4*)(tbase + (size_t)trr * CDIM + c);
            int chunk = c >> 6;
            uint32_t sw = SMEM_SWIZZLE_128B((uint32_t)(trr * 128 + (c & 63) * 2));
            split_store(thi + chunk * 2048, tlo + chunk * 2048, sw, v);
        }
        if (tid < 544) Ssm[tid] = 0.f;
    }
    __syncthreads();

    {
        const int mt  = (wid >> 1) & 1;
        const int ntw = wid & 1;
        const int ks  = wid >> 2;
        float c4[4] = {0.f, 0.f, 0.f, 0.f};

        const int arow = (mt * 16 + (lane & 15)) * 128 + (lane >> 4) * 16;
        const int brow = ((lane & 7) + ((lane >> 4) & 1) * 8) * 128 + ((lane >> 3) & 1) * 16;

        #pragma unroll
        for (int cc = 0; cc < 2; cc++) {
            const int chunk = ks * 2 + cc;
            const uint32_t xb  = XHI_U + chunk * 4096, xbl = XLO_U + chunk * 4096;
            const uint32_t tb  = THI_U + chunk * 2048, tbl = TLO_U + chunk * 2048;
            #pragma unroll
            for (int kk = 0; kk < 4; kk++) {
                const int ksb = kk * 32;
                uint32_t ah[4], al[4], r4[4], r4l[4];
                ldsm4(ah, xb  + SMEM_SWIZZLE_128B((uint32_t)(arow + ksb)));
                ldsm4(al, xbl + SMEM_SWIZZLE_128B((uint32_t)(arow + ksb)));
                ldsm4(r4,  tb  + SMEM_SWIZZLE_128B((uint32_t)(brow + ksb)));
                ldsm4(r4l, tbl + SMEM_SWIZZLE_128B((uint32_t)(brow + ksb)));
                uint32_t bh[2] = {r4[2 * ntw],  r4[2 * ntw + 1]};
                uint32_t bl[2] = {r4l[2 * ntw], r4l[2 * ntw + 1]};
                mma_bf16(c4, ah, bh);
                mma_bf16(c4, ah, bl);
                mma_bf16(c4, al, bh);
            }
        }
        const int r0 = mt * 16 + (lane >> 2);
        const int c0 = ntw * 8 + (lane & 3) * 2;
        atomicAdd(&Ssm[r0 * 17 + c0],           c4[0]);
        atomicAdd(&Ssm[r0 * 17 + c0 + 1],       c4[1]);
        atomicAdd(&Ssm[(r0 + 8) * 17 + c0],     c4[2]);
        atomicAdd(&Ssm[(r0 + 8) * 17 + c0 + 1], c4[3]);
    }
    __syncthreads();

    if (tid < 512) {
        const int h = tid >> 5, j = lane;
        float s = (j <= last) ? Ssm[j * 17 + h] * 0.125f : -INFINITY;
        float m = s;
        #pragma unroll
        for (int off = 16; off; off >>= 1) m = fmaxf(m, __shfl_xor_sync(0xffffffffu, m, off));
        float e = (j <= last) ? __expf(s - m) : 0.f;
        float sum = e;
        #pragma unroll
        for (int off = 16; off; off >>= 1) sum += __shfl_xor_sync(0xffffffffu, sum, off);
        float p = e / sum;
        __nv_bfloat16 ph = __float2bfloat16(p);
        __nv_bfloat16 pl = __float2bfloat16(p - __bfloat162float(ph));
        uint32_t sw = SMEM_SWIZZLE_128B((uint32_t)(h * 128 + j * 2));
        *(__nv_bfloat16*)(pth + sw) = ph;
        *(__nv_bfloat16*)(ptl + sw) = pl;
    }
    __syncthreads();

    {
        const int cbase = wid * 32;
        uint32_t aPh[2][4], aPl[2][4];
        #pragma unroll
        for (int jt = 0; jt < 2; jt++) {
            uint32_t off = SMEM_SWIZZLE_128B((uint32_t)((lane & 15) * 128 + jt * 32 + (lane >> 4) * 16));
            ldsm4(aPh[jt], PTH_U + off);
            ldsm4(aPl[jt], PTL_U + off);
        }
        float c3[4][4];
        #pragma unroll
        for (int nt = 0; nt < 4; nt++)
            #pragma unroll
            for (int q = 0; q < 4; q++) c3[nt][q] = 0.f;

        #pragma unroll
        for (int ct = 0; ct < 2; ct++) {
            const int c0 = cbase + ct * 16;
            const int chunk = c0 >> 6, cin = c0 & 63;
            #pragma unroll
            for (int jt = 0; jt < 2; jt++) {
                const int jrow = (lane & 7) + ((lane >> 3) & 1) * 8 + jt * 16;
                uint32_t off = SMEM_SWIZZLE_128B(
                    (uint32_t)(jrow * 128 + (cin + ((lane >> 4) & 1) * 8) * 2));
                uint32_t bx[4], bxl[4];
                ldsm4t(bx,  XHI_U + chunk * 4096 + off);
                ldsm4t(bxl, XLO_U + chunk * 4096 + off);
                #pragma unroll
                for (int half = 0; half < 2; half++) {
                    const int nt = ct * 2 + half;
                    uint32_t bh[2] = {bx[2 * half],  bx[2 * half + 1]};
                    uint32_t bl[2] = {bxl[2 * half], bxl[2 * half + 1]};
                    mma_bf16(c3[nt], aPh[jt], bh);
                    mma_bf16(c3[nt], aPh[jt], bl);
                    mma_bf16(c3[nt], aPl[jt], bh);
                }
            }
        }
        __nv_bfloat16* Ahp = g_Ah + (size_t)bw * (NH * CDIM);
        __nv_bfloat16* Alp = g_Al + (size_t)bw * (NH * CDIM);
        #pragma unroll
        for (int nt = 0; nt < 4; nt++) {
            const int col = cbase + nt * 8 + (lane & 3) * 2;
            const int r = lane >> 2;
            __nv_bfloat16 h0, l0, h1, l1;
            split1(c3[nt][0], &h0, &l0);
            split1(c3[nt][1], &h1, &l1);
            *(uint32_t*)(Ahp + (size_t)r * CDIM + col) = pkbf(h0, h1);
            *(uint32_t*)(Alp + (size_t)r * CDIM + col) = pkbf(l0, l1);
            split1(c3[nt][2], &h0, &l0);
            split1(c3[nt][3], &h1, &l1);
            *(uint32_t*)(Ahp + (size_t)(r + 8) * CDIM + col) = pkbf(h0, h1);
            *(uint32_t*)(Alp + (size_t)(r + 8) * CDIM + col) = pkbf(l0, l1);
        }
    }
}

// ---------------------------------------------------------------------------
// O GEMM: MTILE=128, 512 threads (16 warps: 4m x 4n), grid (1,8,NH).
// 3-stage cp.async ring, one __syncthreads per chunk.
#define OG_A 0            // 3 stages x (hi 16KB + lo 16KB) = 96KB
#define OG_B 98304        // 3 stages x (hi 8KB + lo 8KB)  = 48KB
#define OG_SMEM (147456 + 1024)

__global__ __launch_bounds__(512)
void k_ogemm_pp(const float* __restrict__ pos) {
    extern __shared__ char dsm[];
    const uint32_t raw = smem_to_u32(dsm);
    const uint32_t padb = (1024u - (raw & 1023u)) & 1023u;
    const uint32_t sb = raw + padb;
    const uint32_t A_BASE = sb + OG_A;
    const uint32_t B_BASE = sb + OG_B;

    const int tid = threadIdx.x, wid = tid >> 5, lane = tid & 31;
    const int row0 = blockIdx.y * 128;
    const int hz = blockIdx.z;

    const int m_w = (wid >> 2) * 32;
    const int n_w = (wid & 3) * 16;

    const int a_row = lane & 15;
    const int a_kb  = (lane >> 4) * 16;
    const int b_row = (lane & 7) + ((lane >> 4) * 8);
    const int b_kb  = ((lane >> 3) & 1) * 16;

    const __nv_bfloat16* Ahp = g_Ah + (size_t)hz * CDIM;
    const __nv_bfloat16* Alp = g_Al + (size_t)hz * CDIM;
    const __nv_bfloat16* Bhp = g_Wh + 2 * (size_t)CDIM * CDIM + (size_t)hz * HD * CDIM;
    const __nv_bfloat16* Blp = g_Wl + 2 * (size_t)CDIM * CDIM + (size_t)hz * HD * CDIM;

    float cfr[2][2][4];
    #pragma unroll
    for (int i = 0; i < 2; i++)
        #pragma unroll
        for (int j = 0; j < 2; j++)
            #pragma unroll
            for (int q = 0; q < 4; q++) cfr[i][j][q] = 0.f;

    // stage issue helper (inline twice in prologue + loop)
    // A stage: 32KB (hi16+lo16); B stage: 16KB (hi8+lo8)
    #define OG_ISSUE(CH) do { \
        const uint32_t _astg = (uint32_t)((CH) % 3) * 32768; \
        const uint32_t _bstg = (uint32_t)((CH) % 3) * 16384; \
        const int _kb = (CH) * 64; \
        _Pragma("unroll") \
        for (int i = tid; i < 1024; i += 512) { \
            int r = i >> 3, g = i & 7; \
            uint32_t dst = A_BASE + _astg + SMEM_SWIZZLE_128B((uint32_t)(r * 128 + g * 16)); \
            cpa16(dst,         Ahp + (size_t)(row0 + r) * (NH * CDIM) + _kb + g * 8); \
            cpa16(dst + 16384, Alp + (size_t)(row0 + r) * (NH * CDIM) + _kb + g * 8); \
        } \
        { \
            int r = tid >> 3, g = tid & 7; \
            uint32_t dst = B_BASE + _bstg + SMEM_SWIZZLE_128B((uint32_t)(r * 128 + g * 16)); \
            cpa16(dst,        Bhp + (size_t)r * CDIM + _kb + g * 8); \
            cpa16(dst + 8192, Blp + (size_t)r * CDIM + _kb + g * 8); \
        } \
        CP_COMMIT(); \
    } while (0)

    OG_ISSUE(0);
    OG_ISSUE(1);

    for (int ch = 0; ch < 16; ch++) {
        if (ch + 1 < 16) { CP_WAIT(1); } else { CP_WAIT(0); }
        __syncthreads();
        if (ch + 2 < 16) OG_ISSUE(ch + 2);

        const uint32_t AH = A_BASE + (uint32_t)(ch % 3) * 32768;
        const uint32_t AL = AH + 16384;
        const uint32_t BH = B_BASE + (uint32_t)(ch % 3) * 16384;
        const uint32_t BL = BH + 8192;

        #pragma unroll
        for (int ks = 0; ks < 4; ks++) {
            const int ksb = ks * 32;
            uint32_t bh[2][2], bl[2][2];
            {
                uint32_t sw = SMEM_SWIZZLE_128B(
                    (uint32_t)((n_w + b_row) * 128 + ksb + b_kb));
                uint32_t r4[4];
                ldsm4(r4, BH + sw);
                bh[0][0] = r4[0]; bh[0][1] = r4[1];
                bh[1][0] = r4[2]; bh[1][1] = r4[3];
                ldsm4(r4, BL + sw);
                bl[0][0] = r4[0]; bl[0][1] = r4[1];
                bl[1][0] = r4[2]; bl[1][1] = r4[3];
            }
            uint32_t ah[2][4], al[2][4];
            #pragma unroll
            for (int mt = 0; mt < 2; mt++) {
                uint32_t sw = SMEM_SWIZZLE_128B(
                    (uint32_t)((m_w + mt * 16 + a_row) * 128 + ksb + a_kb));
                ldsm4(ah[mt], AH + sw);
                ldsm4(al[mt], AL + sw);
            }
            #pragma unroll
            for (int mt = 0; mt < 2; mt++)
                #pragma unroll
                for (int nt = 0; nt < 2; nt++) {
                    mma_bf16(cfr[mt][nt], ah[mt], bh[nt]);
                    mma_bf16(cfr[mt][nt], ah[mt], bl[nt]);
                    mma_bf16(cfr[mt][nt], al[mt], bh[nt]);
                }
        }
    }
    #undef OG_ISSUE

    #pragma unroll
    for (int mt = 0; mt < 2; mt++) {
        #pragma unroll
        for (int nt = 0; nt < 2; nt++) {
            const int cg = hz * HD + n_w + nt * 8 + (lane & 3) * 2;
            #pragma unroll
            for (int half = 0; half < 2; half++) {
                const int r = row0 + m_w + mt * 16 + (lane >> 2) + half * 8;
                const float* pr = pos + (size_t)(r & (WW - 1)) * CDIM + cg;
                float v0 = cfr[mt][nt][half * 2]     + pr[0];
                float v1 = cfr[mt][nt][half * 2 + 1] + pr[1];
                __nv_bfloat16 h0, l0, h1, l1;
                split1(v0, &h0, &l0);
                split1(v1, &h1, &l1);
                *(uint32_t*)(g_oh + (size_t)r * CDIM + cg) = pkbf(h0, h1);
                *(uint32_t*)(g_ol + (size_t)r * CDIM + cg) = pkbf(l0, l1);
            }
        }
    }
}

// ---------------------------------------------------------------------------
// Proj GEMM: MTILE=64, 512 threads (16 warps: 2m x 8n), grid (8,16).
// 3-stage cp.async ring, one __syncthreads per chunk.
#define PJ_A 0            // 3 stages x (hi 8KB + lo 8KB)   = 48KB
#define PJ_B 49152        // 3 stages x (hi 16KB + lo 16KB) = 96KB
#define PJ_SMEM (147456 + 1024)

__global__ __launch_bounds__(512)
void k_proj_pp(float* __restrict__ out) {
    extern __shared__ char dsm[];
    const uint32_t raw = smem_to_u32(dsm);
    const uint32_t padb = (1024u - (raw & 1023u)) & 1023u;
    const uint32_t sb = raw + padb;
    const uint32_t A_BASE = sb + PJ_A;
    const uint32_t B_BASE = sb + PJ_B;

    const int tid = threadIdx.x, wid = tid >> 5, lane = tid & 31;
    const int row0 = blockIdx.y * 64;
    const int col0 = blockIdx.x * 128;

    const int m_w = (wid >> 3) * 32;
    const int n_w = (wid & 7) * 16;

    const int a_row = lane & 15;
    const int a_kb  = (lane >> 4) * 16;
    const int b_row = (lane & 7) + ((lane >> 4) * 8);
    const int b_kb  = ((lane >> 3) & 1) * 16;

    const __nv_bfloat16* Bhp = g_Wh + (size_t)CDIM * CDIM;
    const __nv_bfloat16* Blp = g_Wl + (size_t)CDIM * CDIM;

    float cfr[2][2][4];
    #pragma unroll
    for (int i = 0; i < 2; i++)
        #pragma unroll
        for (int j = 0; j < 2; j++)
            #pragma unroll
            for (int q = 0; q < 4; q++) cfr[i][j][q] = 0.f;

    #define PJ_ISSUE(CH) do { \
        const uint32_t _astg = (uint32_t)((CH) % 3) * 16384; \
        const uint32_t _bstg = (uint32_t)((CH) % 3) * 32768; \
        const int _kb = (CH) * 64; \
        { \
            int r = tid >> 3, g = tid & 7; \
            uint32_t dst = A_BASE + _astg + SMEM_SWIZZLE_128B((uint32_t)(r * 128 + g * 16)); \
            cpa16(dst,        g_oh + (size_t)(row0 + r) * CDIM + _kb + g * 8); \
            cpa16(dst + 8192, g_ol + (size_t)(row0 + r) * CDIM + _kb + g * 8); \
        } \
        _Pragma("unroll") \
        for (int i = tid; i < 1024; i += 512) { \
            int r = i >> 3, g = i & 7; \
            uint32_t dst = B_BASE + _bstg + SMEM_SWIZZLE_128B((uint32_t)(r * 128 + g * 16)); \
            cpa16(dst,         Bhp + (size_t)(col0 + r) * CDIM + _kb + g * 8); \
            cpa16(dst + 16384, Blp + (size_t)(col0 + r) * CDIM + _kb + g * 8); \
        } \
        CP_COMMIT(); \
    } while (0)

    PJ_ISSUE(0);
    PJ_ISSUE(1);

    for (int ch = 0; ch < 16; ch++) {
        if (ch + 1 < 16) { CP_WAIT(1); } else { CP_WAIT(0); }
        __syncthreads();
        if (ch + 2 < 16) PJ_ISSUE(ch + 2);

        const uint32_t AH = A_BASE + (uint32_t)(ch % 3) * 16384;
        const uint32_t AL = AH + 8192;
        const uint32_t BH = B_BASE + (uint32_t)(ch % 3) * 32768;
        const uint32_t BL = BH + 16384;

        #pragma unroll
        for (int ks = 0; ks < 4; ks++) {
            const int ksb = ks * 32;
            uint32_t bh[2][2], bl[2][2];
            {
                uint32_t sw = SMEM_SWIZZLE_128B(
                    (uint32_t)((n_w + b_row) * 128 + ksb + b_kb));
                uint32_t r4[4];
                ldsm4(r4, BH + sw);
                bh[0][0] = r4[0]; bh[0][1] = r4[1];
                bh[1][0] = r4[2]; bh[1][1] = r4[3];
                ldsm4(r4, BL + sw);
                bl[0][0] = r4[0]; bl[0][1] = r4[1];
                bl[1][0] = r4[2]; bl[1][1] = r4[3];
            }
            uint32_t ah[2][4], al[2][4];
            #pragma unroll
            for (int mt = 0; mt < 2; mt++) {
                uint32_t sw = SMEM_SWIZZLE_128B(
                    (uint32_t)((m_w + mt * 16 + a_row) * 128 + ksb + a_kb));
                ldsm4(ah[mt], AH + sw);
                ldsm4(al[mt], AL + sw);
            }
            #pragma unroll
            for (int mt = 0; mt < 2; mt++)
                #pragma unroll
                for (int nt = 0; nt < 2; nt++) {
                    mma_bf16(cfr[mt][nt], ah[mt], bh[nt]);
                    mma_bf16(cfr[mt][nt], ah[mt], bl[nt]);
                    mma_bf16(cfr[mt][nt], al[mt], bh[nt]);
                }
        }
    }
    #undef PJ_ISSUE

    #pragma unroll
    for (int mt = 0; mt < 2; mt++) {
        int r0 = row0 + m_w + mt * 16 + (lane >> 2);
        #pragma unroll
        for (int nt = 0; nt < 2; nt++) {
            int c0 = col0 + n_w + nt * 8 + (lane & 3) * 2;
            *(float2*)(out + (size_t)r0 * CDIM + c0) = make_float2(cfr[mt][nt][0], cfr[mt][nt][1]);
            *(float2*)(out + (size_t)(r0 + 8) * CDIM + c0) = make_float2(cfr[mt][nt][2], cfr[mt][nt][3]);
        }
    }
}

// ---------------------------------------------------------------------------
extern "C" void kernel_launch(void* const* d_in, const int* in_sizes, int n_in,
                              void* d_out, int out_size) {
    const float* x      = (const float*)d_in[0];  // (4,256,32,1024)
    const int*   mask   = (const int*)  d_in[1];  // (4,256,32)
    const float* pos    = (const float*)d_in[2];  // (256,1024)
    const float* attn_w = (const float*)d_in[3];  // (1024,3072)
    const float* proj_w = (const float*)d_in[4];  // (1024,1024)
    float*       out    = (float*)d_out;          // (4,256,1024)

    __nv_bfloat16 *wh, *wl;
    cudaGetSymbolAddress((void**)&wh, g_Wh);
    cudaGetSymbolAddress((void**)&wl, g_Wl);
    const size_t WSZ = (size_t)CDIM * CDIM;

    static int attr_set = 0;
    if (!attr_set) {
        cudaFuncSetAttribute(k_attn_fused4, cudaFuncAttributeMaxDynamicSharedMemorySize, F4_SMEM);
        cudaFuncSetAttribute(k_qt, cudaFuncAttributeMaxDynamicSharedMemorySize, QT_SMEM);
        cudaFuncSetAttribute(k_ogemm_pp, cudaFuncAttributeMaxDynamicSharedMemorySize, OG_SMEM);
        cudaFuncSetAttribute(k_proj_pp, cudaFuncAttributeMaxDynamicSharedMemorySize, PJ_SMEM);
        attr_set = 1;
    }

    // 1) prep: weight splits (4 jobs) + g_last
    {
        dim3 grid(32, 32, 5), blk(32, 8);
        k_prep<<<grid, blk>>>(attn_w, proj_w, mask);
    }

    // 2) fused Q + t (256 threads, R12) -> t fp32
    {
        dim3 grid(1, 8, NH);
        k_qt<<<grid, 256, QT_SMEM>>>(x, wh, wl, wh + 3 * WSZ, wl + 3 * WSZ);
    }

    // 3) fused scores + softmax + mix -> A bf16 planes
    k_attn_fused4<<<BW, 1024, F4_SMEM>>>(x);

    // 4) O = A_h @ Wv_h + pos -> bf16 planes  (3-stage pipeline)
    {
        dim3 grid(1, 8, NH);
        k_ogemm_pp<<<grid, 512, OG_SMEM>>>(pos);
    }

    // 5) out = O+ @ proj^T  (3-stage pipeline)
    {
        dim3 grid(8, 16, 1);
        k_proj_pp<<<grid, 512, PJ_SMEM>>>(out);
    }
}